// round 5
// baseline (speedup 1.0000x reference)
#include <cuda_runtime.h>
#include <math.h>

#define S_LEN 1024
#define BATCH 128
#define DIN 256
#define NQ 8
#define FAN 264      // DIN + NQ
#define NPX 20       // 4 gates * 5 needed params (q in {0,1,5,6,7})

// precomputed x-part of gate pre-activations, S-MAJOR: [s][b][20]
__device__ float g_Px[S_LEN * BATCH * NPX];

#define FULLMASK 0xffffffffu
__device__ __forceinline__ float shfl(float v, int src) { return __shfl_sync(FULLMASK, v, src); }
__device__ __forceinline__ float shflx(float v, int m)  { return __shfl_xor_sync(FULLMASK, v, m); }

// Overflow-safe fast tanh: 1 - 2/(exp(2v)+1). inf-safe at both ends.
__device__ __forceinline__ float ftanh(float v) {
    float e = __expf(2.0f * v);
    return 1.0f - __fdividef(2.0f, e + 1.0f);
}

// ---------------------------------------------------------------------------
// Kernel 1: Px[s,b,g*5+qi] = x[s,b,:] . W_g[q,:256] + b_g[q], q in {0,1,5,6,7}
// block = 160 threads = 20 outputs x 8 k-parts; 4 rows per iteration.
// (R3 version: s-major writes, ~46us)
// ---------------------------------------------------------------------------
__global__ void __launch_bounds__(160) px_kernel(
    const float* __restrict__ x,
    const float* __restrict__ W0, const float* __restrict__ B0,
    const float* __restrict__ W1, const float* __restrict__ B1,
    const float* __restrict__ W2, const float* __restrict__ B2,
    const float* __restrict__ W3, const float* __restrict__ B3)
{
    __shared__ float xsh[4 * 256];
    const int t    = threadIdx.x;
    const int og   = t >> 3;       // 0..19
    const int part = t & 7;        // k = jj*8 + part
    const int g    = og / 5;
    const int qi   = og % 5;
    const int q    = (qi == 0) ? 0 : (qi == 1) ? 1 : (qi == 2) ? 5 : (qi == 3) ? 6 : 7;

    const float* Wp[4] = {W0, W1, W2, W3};
    const float* Bp[4] = {B0, B1, B2, B3};
    const float* Wr = Wp[g] + q * FAN;

    float w[32];
#pragma unroll
    for (int jj = 0; jj < 32; jj++) w[jj] = Wr[jj * 8 + part];
    const float bias = Bp[g][q];

    const int rpb   = (S_LEN * BATCH) / gridDim.x;
    const long base = (long)blockIdx.x * rpb;

    for (int r0 = 0; r0 < rpb; r0 += 4) {
        __syncthreads();
        const float4* src = (const float4*)(x + (base + r0) * DIN);
        for (int i = t; i < 256; i += 160) ((float4*)xsh)[i] = src[i];
        __syncthreads();

        float a0 = 0.f, a1 = 0.f, a2 = 0.f, a3 = 0.f;
#pragma unroll
        for (int jj = 0; jj < 32; jj++) {
            const int k = jj * 8 + part;
            a0 = fmaf(w[jj], xsh[k],       a0);
            a1 = fmaf(w[jj], xsh[256 + k], a1);
            a2 = fmaf(w[jj], xsh[512 + k], a2);
            a3 = fmaf(w[jj], xsh[768 + k], a3);
        }
#pragma unroll
        for (int m = 1; m < 8; m <<= 1) {
            a0 += shflx(a0, m); a1 += shflx(a1, m);
            a2 += shflx(a2, m); a3 += shflx(a3, m);
        }
        if (part == 0) {
            float* dst = &g_Px[(base + r0) * NPX + og];
            dst[0]       = a0 + bias;
            dst[NPX]     = a1 + bias;
            dst[2 * NPX] = a2 + bias;
            dst[3 * NPX] = a3 + bias;
        }
    }
}

// ---------------------------------------------------------------------------
// Kernel 2: sequential recurrence, closed-form probs in y = cos(p) form.
// One warp per batch element; lane = gate*8 + i.
//   - lanes i<5 each compute ONE param p_q (q = {0,1,5,6,7}[i]) and y = cos p
//   - y broadcast within the 8-lane gate group (5 shfl, one stage)
//   - every lane computes prob for qubit j = i with its sign pattern:
//       num = (1+s0 y0)(1+s0 y1)(1+s5 y5)(1+s6 y6)(1+s7 y7)
//       den = 8[(1 + y0 y1) + (y0+y1) y5 y6 y7]
//   - gather 4 gate probs for j (4 shfl), LSTM update replicated on all lanes
// ---------------------------------------------------------------------------
__global__ void __launch_bounds__(32) qlstm_kernel(
    const float* __restrict__ Wf, const float* __restrict__ Wi,
    const float* __restrict__ Wu, const float* __restrict__ Wo,
    float* __restrict__ out)
{
    const int b    = blockIdx.x;
    const int lane = threadIdx.x;
    const int g    = lane >> 3;
    const int i    = lane & 7;     // param slot (i<5) and this lane's qubit j
    const int gb   = lane & 24;

    const int  v5 = (i >> 2) & 1, v6 = (i >> 1) & 1, v7 = i & 1;
    const float s0 = v7 ? -1.f : 1.f;
    const float s5 = v5 ? -1.f : 1.f;
    const float s6 = (v5 ^ v6) ? -1.f : 1.f;
    const float s7 = (v6 ^ v7) ? -1.f : 1.f;

    const float* Wg = (g == 0) ? Wf : (g == 1) ? Wi : (g == 2) ? Wu : Wo;
    const int q = (i == 0) ? 0 : (i == 1) ? 1 : (i == 2) ? 5 : (i == 3) ? 6 : 7;
    const bool par = (i < 5);

    float wh[8];
#pragma unroll
    for (int jj = 0; jj < 8; jj++)
        wh[jj] = par ? Wg[q * FAN + DIN + jj] : 0.f;

    const int poff = g * 5 + i;    // offset within the 20-float row (i<5)
    float h = 0.f, c = 0.f;
    float px0 = par ? g_Px[(long)b * NPX + poff] : 0.f;                  // s=0
    float px1 = par ? g_Px[((long)BATCH + b) * NPX + poff] : 0.f;        // s=1

#pragma unroll 2
    for (int s = 0; s < S_LEN; s++) {
        // prefetch step s+2 (two full loop bodies of slack; 1 LDG per lane)
        float px2 = 0.f;
        if (par) {
            const int sp = (s + 2 < S_LEN) ? s + 2 : S_LEN - 1;
            px2 = g_Px[((long)sp * BATCH + b) * NPX + poff];
        }

        // stage 1: broadcast h
        const float hs0 = shfl(h, 0), hs1 = shfl(h, 1), hs2 = shfl(h, 2), hs3 = shfl(h, 3);
        const float hs4 = shfl(h, 4), hs5 = shfl(h, 5), hs6 = shfl(h, 6), hs7 = shfl(h, 7);

        // one param per lane: two short FMA chains
        float pa = fmaf(wh[0], hs0, px0);
        pa = fmaf(wh[1], hs1, pa);
        pa = fmaf(wh[2], hs2, pa);
        pa = fmaf(wh[3], hs3, pa);
        float pb = wh[4] * hs4;
        pb = fmaf(wh[5], hs5, pb);
        pb = fmaf(wh[6], hs6, pb);
        pb = fmaf(wh[7], hs7, pb);
        const float y = __cosf(pa + pb);

        // stage 2: broadcast the gate's 5 y values within the group
        const float y0 = shfl(y, gb + 0);
        const float y1 = shfl(y, gb + 1);
        const float y5 = shfl(y, gb + 2);
        const float y6 = shfl(y, gb + 3);
        const float y7 = shfl(y, gb + 4);

        const float A   = fmaf(s0, y0, 1.f) * fmaf(s0, y1, 1.f);
        const float num = (A * fmaf(s5, y5, 1.f)) * (fmaf(s6, y6, 1.f) * fmaf(s7, y7, 1.f));
        float den = fmaf(y0 + y1, (y5 * y6) * y7, fmaf(y0, y1, 1.f));
        den = fmaxf(8.0f * den, 1e-30f);
        const float prob = __fdividef(num, den);

        // stage 3: gather the 4 gate probabilities for qubit j = i
        const float pf = shfl(prob, i);
        const float pi = shfl(prob, 8 + i);
        const float pu = shfl(prob, 16 + i);
        const float po = shfl(prob, 24 + i);

        const float gg = ftanh(pu);
        c = fmaf(pf, c, pi * gg);
        h = po * ftanh(c);

        if (lane < NQ)
            out[(long)s * (BATCH * NQ) + b * NQ + lane] = h;

        px0 = px1; px1 = px2;
    }

    if (lane < NQ) {
        const long ob = (long)S_LEN * BATCH * NQ;
        out[ob + b * NQ + lane] = h;                    // h_n
        out[ob + BATCH * NQ + b * NQ + lane] = c;       // c_n
    }
}

// ---------------------------------------------------------------------------
extern "C" void kernel_launch(void* const* d_in, const int* in_sizes, int n_in,
                              void* d_out, int out_size)
{
    const float* x  = (const float*)d_in[0];
    const float* Wf = (const float*)d_in[1];
    const float* bf = (const float*)d_in[2];
    const float* Wi = (const float*)d_in[3];
    const float* bi = (const float*)d_in[4];
    const float* Wu = (const float*)d_in[5];
    const float* bu = (const float*)d_in[6];
    const float* Wo = (const float*)d_in[7];
    const float* bo = (const float*)d_in[8];
    float* out = (float*)d_out;

    px_kernel<<<2048, 160>>>(x, Wf, bf, Wi, bi, Wu, bu, Wo, bo);
    qlstm_kernel<<<BATCH, 32>>>(Wf, Wi, Wu, Wo, out);
}

// round 6
// speedup vs baseline: 1.1187x; 1.1187x over previous
#include <cuda_runtime.h>
#include <math.h>

#define S_LEN 1024
#define BATCH 128
#define DIN 256
#define NQ 8
#define FAN 264      // DIN + NQ
#define NPX 20       // 4 gates * 5 needed params (q in {0,1,5,6,7})

// precomputed x-part of gate pre-activations, S-MAJOR: [s][b][20]
__device__ float g_Px[S_LEN * BATCH * NPX];

#define FULLMASK 0xffffffffu
__device__ __forceinline__ float shfl(float v, int src) { return __shfl_sync(FULLMASK, v, src); }
__device__ __forceinline__ float shflx(float v, int m)  { return __shfl_xor_sync(FULLMASK, v, m); }

// Hardware tanh: single MUFU instruction (sm_75+), ~2^-11 relative error.
__device__ __forceinline__ float ftanh(float v) {
    float r;
    asm("tanh.approx.f32 %0, %1;" : "=f"(r) : "f"(v));
    return r;
}

// ---------------------------------------------------------------------------
// Kernel 1: Px[s,b,g*5+qi] = x[s,b,:] . W_g[q,:256] + b_g[q], q in {0,1,5,6,7}
// block = 160 threads = 20 outputs x 8 k-parts; 4 rows per iteration.
// ---------------------------------------------------------------------------
__global__ void __launch_bounds__(160) px_kernel(
    const float* __restrict__ x,
    const float* __restrict__ W0, const float* __restrict__ B0,
    const float* __restrict__ W1, const float* __restrict__ B1,
    const float* __restrict__ W2, const float* __restrict__ B2,
    const float* __restrict__ W3, const float* __restrict__ B3)
{
    __shared__ float xsh[4 * 256];
    const int t    = threadIdx.x;
    const int og   = t >> 3;       // 0..19
    const int part = t & 7;        // k = jj*8 + part
    const int g    = og / 5;
    const int qi   = og % 5;
    const int q    = (qi == 0) ? 0 : (qi == 1) ? 1 : (qi == 2) ? 5 : (qi == 3) ? 6 : 7;

    const float* Wp[4] = {W0, W1, W2, W3};
    const float* Bp[4] = {B0, B1, B2, B3};
    const float* Wr = Wp[g] + q * FAN;

    float w[32];
#pragma unroll
    for (int jj = 0; jj < 32; jj++) w[jj] = Wr[jj * 8 + part];
    const float bias = Bp[g][q];

    const int rpb   = (S_LEN * BATCH) / gridDim.x;
    const long base = (long)blockIdx.x * rpb;

    for (int r0 = 0; r0 < rpb; r0 += 4) {
        __syncthreads();
        const float4* src = (const float4*)(x + (base + r0) * DIN);
        for (int i = t; i < 256; i += 160) ((float4*)xsh)[i] = src[i];
        __syncthreads();

        float a0 = 0.f, a1 = 0.f, a2 = 0.f, a3 = 0.f;
#pragma unroll
        for (int jj = 0; jj < 32; jj++) {
            const int k = jj * 8 + part;
            a0 = fmaf(w[jj], xsh[k],       a0);
            a1 = fmaf(w[jj], xsh[256 + k], a1);
            a2 = fmaf(w[jj], xsh[512 + k], a2);
            a3 = fmaf(w[jj], xsh[768 + k], a3);
        }
#pragma unroll
        for (int m = 1; m < 8; m <<= 1) {
            a0 += shflx(a0, m); a1 += shflx(a1, m);
            a2 += shflx(a2, m); a3 += shflx(a3, m);
        }
        if (part == 0) {
            float* dst = &g_Px[(base + r0) * NPX + og];
            dst[0]       = a0 + bias;
            dst[NPX]     = a1 + bias;
            dst[2 * NPX] = a2 + bias;
            dst[3 * NPX] = a3 + bias;
        }
    }
}

// ---------------------------------------------------------------------------
// Kernel 2: sequential recurrence, closed-form probs in y = cos(p) form.
// One warp per batch element; lane = gate*8 + i.
//   - lanes i<5 each compute ONE param p_q (q = {0,1,5,6,7}[i]) and y = cos p
//   - y broadcast within the 8-lane gate group (5 shfl, one stage)
//   - every lane computes prob for qubit j = i with its sign pattern:
//       num = (1+s0 y0)(1+s0 y1)(1+s5 y5)(1+s6 y6)(1+s7 y7)
//       den = 8[(1 + y0 y1) + (y0+y1) y5 y6 y7]
//   - gather 4 gate probs for j (4 shfl), LSTM update replicated on all lanes
// ---------------------------------------------------------------------------
__global__ void __launch_bounds__(32) qlstm_kernel(
    const float* __restrict__ Wf, const float* __restrict__ Wi,
    const float* __restrict__ Wu, const float* __restrict__ Wo,
    float* __restrict__ out)
{
    const int b    = blockIdx.x;
    const int lane = threadIdx.x;
    const int g    = lane >> 3;
    const int i    = lane & 7;     // param slot (i<5) and this lane's qubit j
    const int gb   = lane & 24;

    const int  v5 = (i >> 2) & 1, v6 = (i >> 1) & 1, v7 = i & 1;
    const float s0 = v7 ? -1.f : 1.f;
    const float s5 = v5 ? -1.f : 1.f;
    const float s6 = (v5 ^ v6) ? -1.f : 1.f;
    const float s7 = (v6 ^ v7) ? -1.f : 1.f;

    const float* Wg = (g == 0) ? Wf : (g == 1) ? Wi : (g == 2) ? Wu : Wo;
    const int q = (i == 0) ? 0 : (i == 1) ? 1 : (i == 2) ? 5 : (i == 3) ? 6 : 7;
    const bool par = (i < 5);

    float wh[8];
#pragma unroll
    for (int jj = 0; jj < 8; jj++)
        wh[jj] = par ? Wg[q * FAN + DIN + jj] : 0.f;

    const int poff = g * 5 + i;    // offset within the 20-float row (i<5)
    float h = 0.f, c = 0.f;
    float px0 = par ? g_Px[(long)b * NPX + poff] : 0.f;                  // s=0
    float px1 = par ? g_Px[((long)BATCH + b) * NPX + poff] : 0.f;        // s=1

#pragma unroll 2
    for (int s = 0; s < S_LEN; s++) {
        // prefetch step s+2 (two full loop bodies of slack; 1 LDG per lane)
        float px2 = 0.f;
        if (par) {
            const int sp = (s + 2 < S_LEN) ? s + 2 : S_LEN - 1;
            px2 = g_Px[((long)sp * BATCH + b) * NPX + poff];
        }

        // stage 1: broadcast h
        const float hs0 = shfl(h, 0), hs1 = shfl(h, 1), hs2 = shfl(h, 2), hs3 = shfl(h, 3);
        const float hs4 = shfl(h, 4), hs5 = shfl(h, 5), hs6 = shfl(h, 6), hs7 = shfl(h, 7);

        // one param per lane: two short FMA chains
        float pa = fmaf(wh[0], hs0, px0);
        pa = fmaf(wh[1], hs1, pa);
        pa = fmaf(wh[2], hs2, pa);
        pa = fmaf(wh[3], hs3, pa);
        float pb = wh[4] * hs4;
        pb = fmaf(wh[5], hs5, pb);
        pb = fmaf(wh[6], hs6, pb);
        pb = fmaf(wh[7], hs7, pb);
        const float y = __cosf(pa + pb);

        // stage 2: broadcast the gate's 5 y values within the group
        const float y0 = shfl(y, gb + 0);
        const float y1 = shfl(y, gb + 1);
        const float y5 = shfl(y, gb + 2);
        const float y6 = shfl(y, gb + 3);
        const float y7 = shfl(y, gb + 4);

        const float A   = fmaf(s0, y0, 1.f) * fmaf(s0, y1, 1.f);
        const float num = (A * fmaf(s5, y5, 1.f)) * (fmaf(s6, y6, 1.f) * fmaf(s7, y7, 1.f));
        float den = fmaf(y0 + y1, (y5 * y6) * y7, fmaf(y0, y1, 1.f));
        den = fmaxf(8.0f * den, 1e-30f);
        const float prob = __fdividef(num, den);

        // stage 3: gather the 4 gate probabilities for qubit j = i
        const float pf = shfl(prob, i);
        const float pi = shfl(prob, 8 + i);
        const float pu = shfl(prob, 16 + i);
        const float po = shfl(prob, 24 + i);

        const float gg = ftanh(pu);                 // MUFU.TANH
        c = fmaf(pf, c, pi * gg);
        h = po * ftanh(c);                          // MUFU.TANH

        if (lane < NQ)
            out[(long)s * (BATCH * NQ) + b * NQ + lane] = h;

        px0 = px1; px1 = px2;
    }

    if (lane < NQ) {
        const long ob = (long)S_LEN * BATCH * NQ;
        out[ob + b * NQ + lane] = h;                    // h_n
        out[ob + BATCH * NQ + b * NQ + lane] = c;       // c_n
    }
}

// ---------------------------------------------------------------------------
extern "C" void kernel_launch(void* const* d_in, const int* in_sizes, int n_in,
                              void* d_out, int out_size)
{
    const float* x  = (const float*)d_in[0];
    const float* Wf = (const float*)d_in[1];
    const float* bf = (const float*)d_in[2];
    const float* Wi = (const float*)d_in[3];
    const float* bi = (const float*)d_in[4];
    const float* Wu = (const float*)d_in[5];
    const float* bu = (const float*)d_in[6];
    const float* Wo = (const float*)d_in[7];
    const float* bo = (const float*)d_in[8];
    float* out = (float*)d_out;

    px_kernel<<<2048, 160>>>(x, Wf, bf, Wi, bi, Wu, bu, Wo, bo);
    qlstm_kernel<<<BATCH, 32>>>(Wf, Wi, Wu, Wo, out);
}